// round 2
// baseline (speedup 1.0000x reference)
#include <cuda_runtime.h>
#include <math.h>

#define BB 256
#define PP 256
#define TTOT 32
#define NSTEP 31
#define VV 3433
#define HH 512
#define EE 300
#define CC 128
#define G3H 1536

// ---------------- scratch (device globals; no allocation) ----------------
__device__ float g_fp[(size_t)BB * PP * HH];   // feat_proj: 128 MB
__device__ float g_tdt[BB * CC];
__device__ float g_h1a[BB * HH], g_h1b[BB * HH];
__device__ float g_h2a[BB * HH], g_h2b[BB * HH];
__device__ float g_tmp[BB * CC];
__device__ float g_s[BB * CC];
__device__ float g_gx[BB * G3H], g_gh[BB * G3H];
__device__ float g_u[BB * HH];
__device__ float g_att[BB * CC];

// ---------------- generic tiled NT GEMM: C = act(A @ W^T + bias) ----------
// A: MxK row-major (row stride lda), W: NxK row-major (row stride ldw)
template<int BM, int BN, int BK, int TM, int TN, int ACT>
__global__ __launch_bounds__(256) void gemm_nt(
    int M, int N, int K,
    const float* __restrict__ A, int lda,
    const float* __restrict__ W, int ldw,
    const float* __restrict__ bias,
    float* __restrict__ Co, int ldc)
{
    constexpr int TX = BN / TN, TY = BM / TM, NT = TX * TY;
    __shared__ float As[BK][BM + 4];
    __shared__ float Ws[BK][BN + 4];
    const int bm = blockIdx.y * BM, bn = blockIdx.x * BN;
    const int tid = threadIdx.x;
    const int tx = tid % TX, ty = tid / TX;

    float acc[TM][TN];
#pragma unroll
    for (int i = 0; i < TM; i++)
#pragma unroll
        for (int j = 0; j < TN; j++) acc[i][j] = 0.f;

    for (int k0 = 0; k0 < K; k0 += BK) {
#pragma unroll
        for (int i = tid; i < BM * BK; i += NT) {
            int r = i / BK, c = i % BK;
            int m = bm + r, k = k0 + c;
            As[c][r] = (m < M && k < K) ? A[(size_t)m * lda + k] : 0.f;
        }
#pragma unroll
        for (int i = tid; i < BN * BK; i += NT) {
            int r = i / BK, c = i % BK;
            int n = bn + r, k = k0 + c;
            Ws[c][r] = (n < N && k < K) ? W[(size_t)n * ldw + k] : 0.f;
        }
        __syncthreads();
#pragma unroll
        for (int k = 0; k < BK; k++) {
            float a[TM], w[TN];
#pragma unroll
            for (int i = 0; i < TM; i++) a[i] = As[k][ty * TM + i];
#pragma unroll
            for (int j = 0; j < TN; j++) w[j] = Ws[k][tx * TN + j];
#pragma unroll
            for (int i = 0; i < TM; i++)
#pragma unroll
                for (int j = 0; j < TN; j++)
                    acc[i][j] = fmaf(a[i], w[j], acc[i][j]);
        }
        __syncthreads();
    }
#pragma unroll
    for (int i = 0; i < TM; i++) {
        int m = bm + ty * TM + i;
        if (m >= M) continue;
#pragma unroll
        for (int j = 0; j < TN; j++) {
            int n = bn + tx * TN + j;
            if (n >= N) continue;
            float v = acc[i][j];
            if (bias) v += bias[n];
            if (ACT == 1) v = fmaxf(v, 0.f);
            Co[(size_t)m * ldc + n] = v;
        }
    }
}

// ---------- dual-input tanh GEMM: C = tanh(A1@W1^T + A2@W2^T + D) ----------
// M=256, N=128 fixed; BM=BN=32, BK=16, TM=TN=2
__global__ __launch_bounds__(256) void gemm_dual_tanh(
    const float* __restrict__ A1, int lda1, int K1, const float* __restrict__ W1,
    const float* __restrict__ A2, int lda2, int K2, const float* __restrict__ W2,
    const float* __restrict__ D, float* __restrict__ Co)
{
    __shared__ float As[16][36], Ws[16][36];
    const int bm = blockIdx.y * 32, bn = blockIdx.x * 32;
    const int tid = threadIdx.x;
    const int tx = tid % 16, ty = tid / 16;
    float acc[2][2] = {{0.f, 0.f}, {0.f, 0.f}};

    for (int ph = 0; ph < 2; ph++) {
        const float* A = ph ? A2 : A1;
        const float* W = ph ? W2 : W1;
        const int lda = ph ? lda2 : lda1;
        const int K = ph ? K2 : K1;
        for (int k0 = 0; k0 < K; k0 += 16) {
#pragma unroll
            for (int i = tid; i < 512; i += 256) {
                int r = i / 16, c = i % 16;
                int k = k0 + c;
                As[c][r] = (k < K) ? A[(size_t)(bm + r) * lda + k] : 0.f;
                Ws[c][r] = (k < K) ? W[(size_t)(bn + r) * K + k] : 0.f;
            }
            __syncthreads();
#pragma unroll
            for (int k = 0; k < 16; k++) {
                float a0 = As[k][ty * 2], a1 = As[k][ty * 2 + 1];
                float w0 = Ws[k][tx * 2], w1 = Ws[k][tx * 2 + 1];
                acc[0][0] = fmaf(a0, w0, acc[0][0]);
                acc[0][1] = fmaf(a0, w1, acc[0][1]);
                acc[1][0] = fmaf(a1, w0, acc[1][0]);
                acc[1][1] = fmaf(a1, w1, acc[1][1]);
            }
            __syncthreads();
        }
    }
#pragma unroll
    for (int i = 0; i < 2; i++) {
        int m = bm + ty * 2 + i;
#pragma unroll
        for (int j = 0; j < 2; j++) {
            int n = bn + tx * 2 + j;
            float v = acc[i][j] + (D ? D[m * CC + n] : 0.f);
            Co[m * CC + n] = tanhf(v);
        }
    }
}

// ---------- GRU gate pre-activations: gx = X@Wih^T + bih, gh = H@Whh^T + bhh
// M=256, N=1536, K1=128, K2=512; BM=32, BN=64, BK=16, TM=2, TN=4
__global__ __launch_bounds__(256) void gru_gates(
    const float* __restrict__ X, const float* __restrict__ Wih,
    const float* __restrict__ Hp, const float* __restrict__ Whh,
    const float* __restrict__ bih, const float* __restrict__ bhh,
    float* __restrict__ gx, float* __restrict__ gh)
{
    __shared__ float As[16][36], Ws[16][68];
    const int bm = blockIdx.y * 32, bn = blockIdx.x * 64;
    const int tid = threadIdx.x;
    const int tx = tid % 16, ty = tid / 16;
    float ax[2][4] = {}, ah[2][4] = {};

    // phase 1: K=128 (input projection)
    for (int k0 = 0; k0 < 128; k0 += 16) {
#pragma unroll
        for (int i = tid; i < 512; i += 256) {
            int r = i / 16, c = i % 16;
            As[c][r] = X[(size_t)(bm + r) * 128 + k0 + c];
        }
#pragma unroll
        for (int i = tid; i < 1024; i += 256) {
            int r = i / 16, c = i % 16;
            Ws[c][r] = Wih[(size_t)(bn + r) * 128 + k0 + c];
        }
        __syncthreads();
#pragma unroll
        for (int k = 0; k < 16; k++) {
            float a0 = As[k][ty * 2], a1 = As[k][ty * 2 + 1];
#pragma unroll
            for (int j = 0; j < 4; j++) {
                float w = Ws[k][tx * 4 + j];
                ax[0][j] = fmaf(a0, w, ax[0][j]);
                ax[1][j] = fmaf(a1, w, ax[1][j]);
            }
        }
        __syncthreads();
    }
    // phase 2: K=512 (hidden projection)
    for (int k0 = 0; k0 < 512; k0 += 16) {
#pragma unroll
        for (int i = tid; i < 512; i += 256) {
            int r = i / 16, c = i % 16;
            As[c][r] = Hp[(size_t)(bm + r) * 512 + k0 + c];
        }
#pragma unroll
        for (int i = tid; i < 1024; i += 256) {
            int r = i / 16, c = i % 16;
            Ws[c][r] = Whh[(size_t)(bn + r) * 512 + k0 + c];
        }
        __syncthreads();
#pragma unroll
        for (int k = 0; k < 16; k++) {
            float a0 = As[k][ty * 2], a1 = As[k][ty * 2 + 1];
#pragma unroll
            for (int j = 0; j < 4; j++) {
                float w = Ws[k][tx * 4 + j];
                ah[0][j] = fmaf(a0, w, ah[0][j]);
                ah[1][j] = fmaf(a1, w, ah[1][j]);
            }
        }
        __syncthreads();
    }
#pragma unroll
    for (int i = 0; i < 2; i++) {
        int m = bm + ty * 2 + i;
#pragma unroll
        for (int j = 0; j < 4; j++) {
            int n = bn + tx * 4 + j;
            gx[(size_t)m * G3H + n] = ax[i][j] + bih[n];
            gh[(size_t)m * G3H + n] = ah[i][j] + bhh[n];
        }
    }
}

// ---------------- GRU pointwise: hn = (1-z)*n + z*hp ----------------
__global__ __launch_bounds__(256) void gru_pw(
    const float* __restrict__ gx, const float* __restrict__ gh,
    const float* __restrict__ hp, float* __restrict__ hn)
{
    int i = blockIdx.x * 256 + threadIdx.x;   // 0 .. B*H-1
    int b = i >> 9, j = i & 511;
    const float* gxb = gx + (size_t)b * G3H;
    const float* ghb = gh + (size_t)b * G3H;
    float r = 1.f / (1.f + __expf(-(gxb[j] + ghb[j])));
    float z = 1.f / (1.f + __expf(-(gxb[j + HH] + ghb[j + HH])));
    float n = tanhf(gxb[j + 2 * HH] + r * ghb[j + 2 * HH]);
    hn[i] = (1.f - z) * n + z * hp[i];
}

// ---------------- fused attention: scores + softmax + attended -------------
// one block per batch row b, 256 threads
__global__ __launch_bounds__(256) void attn_kernel(
    const float* __restrict__ fp, const float* __restrict__ u,
    const float* __restrict__ wa, const float* __restrict__ cf,
    float* __restrict__ att, float* __restrict__ outA, int t)
{
    const int b = blockIdx.x;
    const int tid = threadIdx.x;
    __shared__ float us[HH], was[HH], sc[PP], red[PP];

    for (int i = tid; i < HH; i += 256) {
        us[i] = u[(size_t)b * HH + i];
        was[i] = wa[i];
    }
    __syncthreads();

    const int w = tid >> 5, l = tid & 31;
    const float* fpb = fp + (size_t)b * PP * HH;
    for (int p = w; p < PP; p += 8) {
        const float* row = fpb + (size_t)p * HH;
        float ssum = 0.f;
        for (int h = l; h < HH; h += 32)
            ssum += was[h] * tanhf(row[h] + us[h]);
#pragma unroll
        for (int o = 16; o > 0; o >>= 1)
            ssum += __shfl_down_sync(0xffffffffu, ssum, o);
        if (l == 0) sc[p] = ssum;
    }
    __syncthreads();

    float v = sc[tid];
    red[tid] = v;
    __syncthreads();
    for (int st = 128; st > 0; st >>= 1) {
        if (tid < st) red[tid] = fmaxf(red[tid], red[tid + st]);
        __syncthreads();
    }
    float mx = red[0];
    __syncthreads();
    float e = __expf(v - mx);
    red[tid] = e;
    __syncthreads();
    for (int st = 128; st > 0; st >>= 1) {
        if (tid < st) red[tid] += red[tid + st];
        __syncthreads();
    }
    float mask = e * (1.f / red[0]);
    sc[tid] = mask;
    outA[((size_t)b * PP + tid) * NSTEP + t] = mask;
    __syncthreads();

    // attended[b,c] = sum_p mask[p] * cf[b,p,c]
    const int c = tid & (CC - 1);
    const int half = tid >> 7;
    const float* cfb = cf + (size_t)b * PP * CC;
    float a = 0.f;
    for (int p = half * 128; p < half * 128 + 128; p++)
        a += sc[p] * cfb[(size_t)p * CC + c];
    red[tid] = a;
    __syncthreads();
    if (tid < CC) att[(size_t)b * CC + tid] = red[tid] + red[tid + 128];
}

__global__ __launch_bounds__(256) void zero2(float* a, float* b) {
    int i = blockIdx.x * 256 + threadIdx.x;
    a[i] = 0.f;
    b[i] = 0.f;
}

// ---------------------------- host launcher -------------------------------
extern "C" void kernel_launch(void* const* d_in, const int* in_sizes, int n_in,
                              void* d_out, int out_size)
{
    const float* word_embs = (const float*)d_in[0];
    const float* t_feat    = (const float*)d_in[1];
    const float* c_feats   = (const float*)d_in[2];
    const int o = n_in - 20;   // robust to num_words being present or not
    const float* W_td1 = (const float*)d_in[o + 0];
    const float* W_td2 = (const float*)d_in[o + 1];
    const float* W_td3 = (const float*)d_in[o + 2];
    const float* W_td  = (const float*)d_in[o + 3];
    const float* W1_ih = (const float*)d_in[o + 4];
    const float* W1_hh = (const float*)d_in[o + 5];
    const float* b1_ih = (const float*)d_in[o + 6];
    const float* b1_hh = (const float*)d_in[o + 7];
    const float* W_feat = (const float*)d_in[o + 8];
    const float* W_hidd = (const float*)d_in[o + 9];
    const float* W_att  = (const float*)d_in[o + 10];
    const float* W_l1 = (const float*)d_in[o + 11];
    const float* W_l2 = (const float*)d_in[o + 12];
    const float* W_l  = (const float*)d_in[o + 13];
    const float* W2_ih = (const float*)d_in[o + 14];
    const float* W2_hh = (const float*)d_in[o + 15];
    const float* b2_ih = (const float*)d_in[o + 16];
    const float* b2_hh = (const float*)d_in[o + 17];
    const float* W_cls = (const float*)d_in[o + 18];
    const float* b_cls = (const float*)d_in[o + 19];

    float* out_lang = (float*)d_out;                               // (B, 31, V)
    float* out_att  = out_lang + (size_t)BB * NSTEP * VV;          // (B, P, 31)

    float *fp, *tdt, *h1a, *h1b, *h2a, *h2b, *tmp, *s, *gx, *gh, *u, *att;
    cudaGetSymbolAddress((void**)&fp,  g_fp);
    cudaGetSymbolAddress((void**)&tdt, g_tdt);
    cudaGetSymbolAddress((void**)&h1a, g_h1a);
    cudaGetSymbolAddress((void**)&h1b, g_h1b);
    cudaGetSymbolAddress((void**)&h2a, g_h2a);
    cudaGetSymbolAddress((void**)&h2b, g_h2b);
    cudaGetSymbolAddress((void**)&tmp, g_tmp);
    cudaGetSymbolAddress((void**)&s,   g_s);
    cudaGetSymbolAddress((void**)&gx,  g_gx);
    cudaGetSymbolAddress((void**)&gh,  g_gh);
    cudaGetSymbolAddress((void**)&u,   g_u);
    cudaGetSymbolAddress((void**)&att, g_att);

    // init hidden states
    zero2<<<(BB * HH) / 256, 256>>>(h1a, h2a);
    // td_t = t_feat @ W_td2^T   (256 x 128, K=128)
    gemm_nt<32, 32, 16, 2, 2, 0><<<dim3(CC / 32, BB / 32), 256>>>(
        BB, CC, CC, t_feat, CC, W_td2, CC, nullptr, tdt, CC);
    // feat_proj = c_feats @ W_feat^T   (65536 x 512, K=128)
    gemm_nt<64, 64, 16, 4, 4, 0><<<dim3(HH / 64, (BB * PP) / 64), 256>>>(
        BB * PP, HH, CC, c_feats, CC, W_feat, CC, nullptr, fp, HH);

    for (int t = 0; t < NSTEP; t++) {
        const float* h1p = (t & 1) ? h1b : h1a;
        float*       h1n = (t & 1) ? h1a : h1b;
        const float* h2p = (t & 1) ? h2b : h2a;
        float*       h2n = (t & 1) ? h2a : h2b;

        // tmp = tanh(x_t@W_td3^T + h2p@W_td1^T + td_t)
        gemm_dual_tanh<<<dim3(4, 8), 256>>>(
            word_embs + (size_t)t * EE, TTOT * EE, EE, W_td3,
            h2p, HH, HH, W_td1, tdt, tmp);
        // s = relu(tmp @ W_td^T)
        gemm_nt<32, 32, 16, 2, 2, 1><<<dim3(4, 8), 256>>>(
            BB, CC, CC, tmp, CC, W_td, CC, nullptr, s, CC);
        // GRU 1
        gru_gates<<<dim3(G3H / 64, BB / 32), 256>>>(
            s, W1_ih, h1p, W1_hh, b1_ih, b1_hh, gx, gh);
        gru_pw<<<(BB * HH) / 256, 256>>>(gx, gh, h1p, h1n);
        // u = h1 @ W_hidd^T
        gemm_nt<32, 64, 16, 2, 4, 0><<<dim3(HH / 64, BB / 32), 256>>>(
            BB, HH, HH, h1n, HH, W_hidd, HH, nullptr, u, HH);
        // attention (scores + softmax + attended + mask output)
        attn_kernel<<<BB, 256>>>(fp, u, W_att, c_feats, att, out_att, t);
        // tmp = tanh(att@W_l1^T + h1@W_l2^T)
        gemm_dual_tanh<<<dim3(4, 8), 256>>>(
            att, CC, CC, W_l1, h1n, HH, HH, W_l2, nullptr, tmp);
        // l = relu(tmp @ W_l^T)
        gemm_nt<32, 32, 16, 2, 2, 1><<<dim3(4, 8), 256>>>(
            BB, CC, CC, tmp, CC, W_l, CC, nullptr, s, CC);
        // GRU 2
        gru_gates<<<dim3(G3H / 64, BB / 32), 256>>>(
            s, W2_ih, h2p, W2_hh, b2_ih, b2_hh, gx, gh);
        gru_pw<<<(BB * HH) / 256, 256>>>(gx, gh, h2p, h2n);
        // logits = h2 @ W_cls^T + b_cls  -> out_lang[:, t, :]
        gemm_nt<64, 64, 16, 4, 4, 0><<<dim3((VV + 63) / 64, BB / 64), 256>>>(
            BB, VV, HH, h2n, HH, W_cls, HH, b_cls,
            out_lang + (size_t)t * VV, NSTEP * VV);
    }
}